// round 1
// baseline (speedup 1.0000x reference)
#include <cuda_runtime.h>
#include <math.h>

#define BATCH 256
#define C1_IN 3
#define C1_OUT 6
#define H_IN 250
#define C1_H 124          // conv1 out H/W
#define P1_H 123          // pool1 out H/W
#define C2_OUT 15
#define C2_H 62           // conv2 out H/W
#define P2_H 61           // pool2 out H/W
#define K_FC1 55815       // 15*61*61
#define N_FC1 120
#define N_FC2 84
#define KSPLIT 64
#define KCHUNK 873        // ceil(55815/64)

// Scratch (static device globals — allocation-free)
__device__ float g_conv1[(size_t)BATCH * C1_OUT * C1_H * C1_H];   // 94.5 MB
__device__ float g_conv2[(size_t)BATCH * C2_OUT * C2_H * C2_H];   // 59 MB
__device__ float g_fc1_part[KSPLIT][BATCH * N_FC1];               // 7.9 MB

// ---------------------------------------------------------------------------
// conv1: 3->6, 5x5, stride 2, pad 1, + ReLU
// ---------------------------------------------------------------------------
__global__ void conv1_kernel(const float* __restrict__ x,
                             const float* __restrict__ w1,
                             const float* __restrict__ b1) {
    const int bz = blockIdx.z;
    const int b = bz / C1_OUT, oc = bz % C1_OUT;
    const int ox0 = blockIdx.x * 16, oy0 = blockIdx.y * 16;

    __shared__ float S[3][35][35];
    __shared__ float W[3][5][5];

    const int tid = threadIdx.y * 16 + threadIdx.x;
    if (tid < 75) ((float*)W)[tid] = w1[oc * 75 + tid];

    const int iy0 = oy0 * 2 - 1, ix0 = ox0 * 2 - 1;
    const float* xb = x + (size_t)b * C1_IN * H_IN * H_IN;

    for (int idx = tid; idx < 3 * 35 * 35; idx += 256) {
        int c = idx / 1225, r = idx - c * 1225;
        int y = r / 35, xx = r - y * 35;
        int iy = iy0 + y, ix = ix0 + xx;
        float v = 0.f;
        if (iy >= 0 && iy < H_IN && ix >= 0 && ix < H_IN)
            v = xb[(c * H_IN + iy) * H_IN + ix];
        S[c][y][xx] = v;
    }
    __syncthreads();

    const int ox = ox0 + threadIdx.x, oy = oy0 + threadIdx.y;
    if (ox >= C1_H || oy >= C1_H) return;

    float acc = b1[oc];
#pragma unroll
    for (int c = 0; c < 3; c++)
#pragma unroll
        for (int ky = 0; ky < 5; ky++)
#pragma unroll
            for (int kx = 0; kx < 5; kx++)
                acc += S[c][threadIdx.y * 2 + ky][threadIdx.x * 2 + kx] * W[c][ky][kx];

    g_conv1[((size_t)(b * C1_OUT + oc) * C1_H + oy) * C1_H + ox] = fmaxf(acc, 0.f);
}

// ---------------------------------------------------------------------------
// conv2: maxpool(2,s1) fused into smem load; 6->15, 3x3, stride 2, pad 1, + ReLU
// ---------------------------------------------------------------------------
__global__ void conv2_kernel(const float* __restrict__ w2,
                             const float* __restrict__ b2) {
    const int bz = blockIdx.z;
    const int b = bz / C2_OUT, oc = bz % C2_OUT;
    const int ox0 = blockIdx.x * 16, oy0 = blockIdx.y * 16;

    __shared__ float P[6][33][33];
    __shared__ float W[6][3][3];

    const int tid = threadIdx.y * 16 + threadIdx.x;
    if (tid < 54) ((float*)W)[tid] = w2[oc * 54 + tid];

    const int py0 = oy0 * 2 - 1, px0 = ox0 * 2 - 1;
    const float* cb = g_conv1 + (size_t)b * C1_OUT * C1_H * C1_H;

    for (int idx = tid; idx < 6 * 33 * 33; idx += 256) {
        int c = idx / 1089, r = idx - c * 1089;
        int y = r / 33, xx = r - y * 33;
        int py = py0 + y, px = px0 + xx;
        float v = 0.f;
        if (py >= 0 && py < P1_H && px >= 0 && px < P1_H) {
            const float* p = cb + (c * C1_H + py) * C1_H + px;
            v = fmaxf(fmaxf(p[0], p[1]), fmaxf(p[C1_H], p[C1_H + 1]));
        }
        P[c][y][xx] = v;
    }
    __syncthreads();

    const int ox = ox0 + threadIdx.x, oy = oy0 + threadIdx.y;
    if (ox >= C2_H || oy >= C2_H) return;

    float acc = b2[oc];
#pragma unroll
    for (int c = 0; c < 6; c++)
#pragma unroll
        for (int ky = 0; ky < 3; ky++)
#pragma unroll
            for (int kx = 0; kx < 3; kx++)
                acc += P[c][threadIdx.y * 2 + ky][threadIdx.x * 2 + kx] * W[c][ky][kx];

    g_conv2[((size_t)(b * C2_OUT + oc) * C2_H + oy) * C2_H + ox] = fmaxf(acc, 0.f);
}

// ---------------------------------------------------------------------------
// FC1 split-K GEMM (M=256, N=120, K=55815), maxpool-2 fused into the A load.
// BM=64, BN=120, BK=32. Grid (4, KSPLIT). Writes deterministic partials.
// ---------------------------------------------------------------------------
__global__ void fc1_kernel(const float* __restrict__ fc1_w) {
    const int m0 = blockIdx.x * 64;
    const int k0 = blockIdx.y * KCHUNK;
    const int kend = min(k0 + KCHUNK, K_FC1);

    __shared__ float As[64][33];
    __shared__ float Bs[32][120];

    const int tid = threadIdx.x;
    const int row = tid >> 2;       // 0..63
    const int cg = tid & 3;         // 0..3 -> 30 cols each

    float acc[30];
#pragma unroll
    for (int j = 0; j < 30; j++) acc[j] = 0.f;

    for (int kb = k0; kb < kend; kb += 32) {
        // A tile: 64 rows x 32 k (maxpool of g_conv2 on the fly)
#pragma unroll
        for (int i = 0; i < 8; i++) {
            int idx = tid + i * 256;
            int r = idx >> 5, kk = idx & 31;
            int k = kb + kk;
            float v = 0.f;
            if (k < kend) {
                int c = k / 3721;
                int rem = k - c * 3721;
                int y = rem / 61;
                int xx = rem - y * 61;
                const float* p = g_conv2 +
                    ((size_t)((m0 + r) * C2_OUT + c) * C2_H + y) * C2_H + xx;
                v = fmaxf(fmaxf(p[0], p[1]), fmaxf(p[C2_H], p[C2_H + 1]));
            }
            As[r][kk] = v;
        }
        // B tile: 120 n x 32 k (fc1_w is [120, 55815] row-major)
#pragma unroll
        for (int i = 0; i < 15; i++) {
            int idx = tid + i * 256;
            int n = idx >> 5, kk = idx & 31;
            int k = kb + kk;
            Bs[kk][n] = (k < kend) ? fc1_w[(size_t)n * K_FC1 + k] : 0.f;
        }
        __syncthreads();

#pragma unroll
        for (int kk = 0; kk < 32; kk++) {
            float a = As[row][kk];
#pragma unroll
            for (int j = 0; j < 30; j++)
                acc[j] += a * Bs[kk][cg * 30 + j];
        }
        __syncthreads();
    }

    float* dst = &g_fc1_part[blockIdx.y][(m0 + row) * N_FC1 + cg * 30];
#pragma unroll
    for (int j = 0; j < 30; j++) dst[j] = acc[j];
}

// ---------------------------------------------------------------------------
// Head: reduce FC1 partials + bias + ReLU, FC2+ReLU, FC3, quantum statevector
// sim (4 qubits, RX encode, 2x[RY layer + CZ chain], <Z0>,<Z1>), softmax.
// One block per batch sample.
// ---------------------------------------------------------------------------
__global__ void head_kernel(const float* __restrict__ fc1_b,
                            const float* __restrict__ fc2_w,
                            const float* __restrict__ fc2_b,
                            const float* __restrict__ fc3_w,
                            const float* __restrict__ fc3_b,
                            const float* __restrict__ qw,
                            float* __restrict__ out) {
    const int b = blockIdx.x;
    __shared__ float h1[N_FC1];
    __shared__ float h2[N_FC2];
    __shared__ float ang[4];
    const int t = threadIdx.x;

    if (t < N_FC1) {
        float s = fc1_b[t];
#pragma unroll 8
        for (int j = 0; j < KSPLIT; j++) s += g_fc1_part[j][b * N_FC1 + t];
        h1[t] = fmaxf(s, 0.f);
    }
    __syncthreads();

    if (t < N_FC2) {
        float a = fc2_b[t];
#pragma unroll 8
        for (int k = 0; k < N_FC1; k++) a += h1[k] * fc2_w[t * N_FC1 + k];
        h2[t] = fmaxf(a, 0.f);
    }
    __syncthreads();

    if (t < 4) {
        float a = fc3_b[t];
#pragma unroll 4
        for (int k = 0; k < N_FC2; k++) a += h2[k] * fc3_w[t * N_FC2 + k];
        ang[t] = a;
    }
    __syncthreads();

    if (t == 0) {
        float sr[16], si[16];
#pragma unroll
        for (int i = 0; i < 16; i++) { sr[i] = 0.f; si[i] = 0.f; }
        sr[0] = 1.f;

        // RX encoding: gate [[c, -i s],[-i s, c]], wire q targets bit (3-q)
#pragma unroll
        for (int q = 0; q < 4; q++) {
            float th = ang[q] * 0.5f;
            float c = cosf(th), s = sinf(th);
            const int bit = 1 << (3 - q);
#pragma unroll
            for (int i0 = 0; i0 < 16; i0++) {
                if (i0 & bit) continue;
                int i1 = i0 | bit;
                float a0r = sr[i0], a0i = si[i0], a1r = sr[i1], a1i = si[i1];
                sr[i0] = c * a0r + s * a1i;  si[i0] = c * a0i - s * a1r;
                sr[i1] = c * a1r + s * a0i;  si[i1] = c * a1i - s * a0r;
            }
        }
        // DEPTH=2: RY layer (real gate [[c,-s],[s,c]]) + CZ chain
        int w = 0;
#pragma unroll
        for (int d = 0; d < 2; d++) {
#pragma unroll
            for (int q = 0; q < 4; q++) {
                float th = qw[w++] * 0.5f;
                float c = cosf(th), s = sinf(th);
                const int bit = 1 << (3 - q);
#pragma unroll
                for (int i0 = 0; i0 < 16; i0++) {
                    if (i0 & bit) continue;
                    int i1 = i0 | bit;
                    float a0r = sr[i0], a0i = si[i0], a1r = sr[i1], a1i = si[i1];
                    sr[i0] = c * a0r - s * a1r;  si[i0] = c * a0i - s * a1i;
                    sr[i1] = s * a0r + c * a1r;  si[i1] = s * a0i + c * a1i;
                }
            }
#pragma unroll
            for (int q = 0; q < 3; q++) {
                const int m1 = 1 << (3 - q), m2 = 1 << (2 - q);
#pragma unroll
                for (int i = 0; i < 16; i++)
                    if ((i & m1) && (i & m2)) { sr[i] = -sr[i]; si[i] = -si[i]; }
            }
        }
        float l0 = 0.f, l1 = 0.f;
#pragma unroll
        for (int i = 0; i < 16; i++) {
            float p = sr[i] * sr[i] + si[i] * si[i];
            l0 += (i & 8) ? -p : p;
            l1 += (i & 4) ? -p : p;
        }
        float m = fmaxf(l0, l1);
        float e0 = __expf(l0 - m), e1 = __expf(l1 - m);
        float inv = 1.f / (e0 + e1);
        out[b * 2 + 0] = e0 * inv;
        out[b * 2 + 1] = e1 * inv;
    }
}

// ---------------------------------------------------------------------------
extern "C" void kernel_launch(void* const* d_in, const int* in_sizes, int n_in,
                              void* d_out, int out_size) {
    const float* x     = (const float*)d_in[0];
    const float* w1    = (const float*)d_in[1];
    const float* b1    = (const float*)d_in[2];
    const float* w2    = (const float*)d_in[3];
    const float* b2    = (const float*)d_in[4];
    const float* fc1_w = (const float*)d_in[5];
    const float* fc1_b = (const float*)d_in[6];
    const float* fc2_w = (const float*)d_in[7];
    const float* fc2_b = (const float*)d_in[8];
    const float* fc3_w = (const float*)d_in[9];
    const float* fc3_b = (const float*)d_in[10];
    const float* qw    = (const float*)d_in[11];
    float* out = (float*)d_out;

    dim3 blk(16, 16);
    conv1_kernel<<<dim3(8, 8, BATCH * C1_OUT), blk>>>(x, w1, b1);
    conv2_kernel<<<dim3(4, 4, BATCH * C2_OUT), blk>>>(w2, b2);
    fc1_kernel<<<dim3(4, KSPLIT), 256>>>(fc1_w);
    head_kernel<<<BATCH, 128>>>(fc1_b, fc2_w, fc2_b, fc3_w, fc3_b, qw, out);
}

// round 2
// speedup vs baseline: 2.8690x; 2.8690x over previous
#include <cuda_runtime.h>
#include <math.h>

#define BATCH 256
#define C1_IN 3
#define C1_OUT 6
#define H_IN 250
#define C1_H 124          // conv1 out H/W
#define P1_H 123          // pool1 out H/W
#define C2_OUT 15
#define C2_H 62           // conv2 out H/W
#define P2_H 61           // pool2 out H/W
#define K_FC1 55815       // 15*61*61
#define N_FC1 120
#define N_FC2 84
#define KSPLIT 74
#define KCHUNK 755        // ceil(55815/74)

// Scratch (static device globals — allocation-free)
__device__ float g_conv1[(size_t)BATCH * C1_OUT * C1_H * C1_H];   // 94.5 MB
__device__ float g_conv2[(size_t)BATCH * C2_OUT * C2_H * C2_H];   // 59 MB
__device__ float g_fc1_part[KSPLIT][BATCH * N_FC1];               // 9.1 MB

// packed f32x2 helpers
#define BPACK(dst, f) asm("mov.b64 %0, {%1, %1};" : "=l"(dst) : "r"(__float_as_uint(f)))
#define PACK2(dst, lo, hi) asm("mov.b64 %0, {%1, %2};" : "=l"(dst) : "r"(__float_as_uint(lo)), "r"(__float_as_uint(hi)))
#define FMA2(acc, a, b) asm("fma.rn.f32x2 %0, %1, %2, %0;" : "+l"(acc) : "l"(a), "l"(b))

// ---------------------------------------------------------------------------
// conv1: 3->6, 5x5, stride 2, pad 1, + ReLU.  One block = 32x32 output tile,
// ALL 6 output channels in registers (2x2 px * 6 oc = 24 accumulators).
// Dynamic smem: S[3][67][67] + W[450] + Bias[6]
// ---------------------------------------------------------------------------
#define C1_SW 67
#define C1_S_ELEMS (3 * C1_SW * C1_SW)
#define C1_SMEM_BYTES ((C1_S_ELEMS + 450 + 6 + 8) * 4)

__global__ __launch_bounds__(256) void conv1_kernel(const float* __restrict__ x,
                                                    const float* __restrict__ w1,
                                                    const float* __restrict__ b1) {
    extern __shared__ float sm1[];
    float* S = sm1;                      // [3][67][67]
    float* W = sm1 + C1_S_ELEMS;         // [6][3][5][5]
    float* Bias = W + 450;

    const int b = blockIdx.z;
    const int ox0 = blockIdx.x * 32, oy0 = blockIdx.y * 32;
    const int tx = threadIdx.x, ty = threadIdx.y;
    const int tid = ty * 16 + tx;

    for (int i = tid; i < 450; i += 256) W[i] = w1[i];
    if (tid < 6) Bias[tid] = b1[tid];

    const int iy0 = oy0 * 2 - 1, ix0 = ox0 * 2 - 1;
    const float* xb = x + (size_t)b * C1_IN * H_IN * H_IN;

    for (int idx = tid; idx < C1_S_ELEMS; idx += 256) {
        int c = idx / (C1_SW * C1_SW), r = idx % (C1_SW * C1_SW);
        int y = r / C1_SW, xx = r % C1_SW;
        int iy = iy0 + y, ix = ix0 + xx;
        float v = 0.f;
        if (iy >= 0 && iy < H_IN && ix >= 0 && ix < H_IN)
            v = xb[(c * H_IN + iy) * H_IN + ix];
        S[idx] = v;
    }
    __syncthreads();

    float acc[4][6];
#pragma unroll
    for (int p = 0; p < 4; p++)
#pragma unroll
        for (int oc = 0; oc < 6; oc++) acc[p][oc] = 0.f;

#pragma unroll
    for (int c = 0; c < 3; c++) {
        const float* Sc = S + c * C1_SW * C1_SW;
#pragma unroll
        for (int ky = 0; ky < 5; ky++) {
            const float* r0 = Sc + (ty * 2 + ky) * C1_SW;
            const float* r1 = Sc + (ty * 2 + 32 + ky) * C1_SW;
#pragma unroll
            for (int kx = 0; kx < 5; kx++) {
                float s0 = r0[tx * 2 + kx];
                float s1 = r0[tx * 2 + 32 + kx];
                float s2 = r1[tx * 2 + kx];
                float s3 = r1[tx * 2 + 32 + kx];
#pragma unroll
                for (int oc = 0; oc < 6; oc++) {
                    float w = W[((oc * 3 + c) * 5 + ky) * 5 + kx];
                    acc[0][oc] += s0 * w;
                    acc[1][oc] += s1 * w;
                    acc[2][oc] += s2 * w;
                    acc[3][oc] += s3 * w;
                }
            }
        }
    }

#pragma unroll
    for (int p = 0; p < 4; p++) {
        int ox = ox0 + tx + (p & 1) * 16;
        int oy = oy0 + ty + (p >> 1) * 16;
        if (ox < C1_H && oy < C1_H) {
#pragma unroll
            for (int oc = 0; oc < 6; oc++)
                g_conv1[((size_t)(b * C1_OUT + oc) * C1_H + oy) * C1_H + ox] =
                    fmaxf(acc[p][oc] + Bias[oc], 0.f);
        }
    }
}

// ---------------------------------------------------------------------------
// conv2: maxpool(2,s1) fused into smem load; 6->15, 3x3, stride 2, pad 1, ReLU
// One block = 32x32 output tile, all 15 oc (4 px * 15 oc = 60 accumulators).
// Dynamic smem: P[6][65][65] + W[810] + Bias[15]
// ---------------------------------------------------------------------------
#define C2_SW 65
#define C2_P_ELEMS (6 * C2_SW * C2_SW)
#define C2_SMEM_BYTES ((C2_P_ELEMS + 810 + 15 + 8) * 4)

__global__ __launch_bounds__(256) void conv2_kernel(const float* __restrict__ w2,
                                                    const float* __restrict__ b2) {
    extern __shared__ float sm2[];
    float* P = sm2;                      // [6][65][65]
    float* W = sm2 + C2_P_ELEMS;         // [15][6][3][3]
    float* Bias = W + 810;

    const int b = blockIdx.z;
    const int ox0 = blockIdx.x * 32, oy0 = blockIdx.y * 32;
    const int tx = threadIdx.x, ty = threadIdx.y;
    const int tid = ty * 16 + tx;

    for (int i = tid; i < 810; i += 256) W[i] = w2[i];
    if (tid < 15) Bias[tid] = b2[tid];

    const int py0 = oy0 * 2 - 1, px0 = ox0 * 2 - 1;
    const float* cb = g_conv1 + (size_t)b * C1_OUT * C1_H * C1_H;

    for (int idx = tid; idx < C2_P_ELEMS; idx += 256) {
        int c = idx / (C2_SW * C2_SW), r = idx % (C2_SW * C2_SW);
        int y = r / C2_SW, xx = r % C2_SW;
        int py = py0 + y, px = px0 + xx;
        float v = 0.f;
        if (py >= 0 && py < P1_H && px >= 0 && px < P1_H) {
            const float* p = cb + (c * C1_H + py) * C1_H + px;
            v = fmaxf(fmaxf(p[0], p[1]), fmaxf(p[C1_H], p[C1_H + 1]));
        }
        P[idx] = v;
    }
    __syncthreads();

    float acc[4][15];
#pragma unroll
    for (int p = 0; p < 4; p++)
#pragma unroll
        for (int oc = 0; oc < 15; oc++) acc[p][oc] = 0.f;

#pragma unroll
    for (int c = 0; c < 6; c++) {
        const float* Pc = P + c * C2_SW * C2_SW;
#pragma unroll
        for (int ky = 0; ky < 3; ky++) {
            const float* r0 = Pc + (ty * 2 + ky) * C2_SW;
            const float* r1 = Pc + (ty * 2 + 32 + ky) * C2_SW;
#pragma unroll
            for (int kx = 0; kx < 3; kx++) {
                float s0 = r0[tx * 2 + kx];
                float s1 = r0[tx * 2 + 32 + kx];
                float s2 = r1[tx * 2 + kx];
                float s3 = r1[tx * 2 + 32 + kx];
#pragma unroll
                for (int oc = 0; oc < 15; oc++) {
                    float w = W[((oc * 6 + c) * 3 + ky) * 3 + kx];
                    acc[0][oc] += s0 * w;
                    acc[1][oc] += s1 * w;
                    acc[2][oc] += s2 * w;
                    acc[3][oc] += s3 * w;
                }
            }
        }
    }

#pragma unroll
    for (int p = 0; p < 4; p++) {
        int ox = ox0 + tx + (p & 1) * 16;
        int oy = oy0 + ty + (p >> 1) * 16;
        if (ox < C2_H && oy < C2_H) {
#pragma unroll
            for (int oc = 0; oc < 15; oc++)
                g_conv2[((size_t)(b * C2_OUT + oc) * C2_H + oy) * C2_H + ox] =
                    fmaxf(acc[p][oc] + Bias[oc], 0.f);
        }
    }
}

// ---------------------------------------------------------------------------
// FC1 split-K GEMM (M=256, N=120, K=55815), maxpool-2 fused into the A load.
// BM=64, BN=120, BK=32, 240 threads, thread tile 4x8, packed fma.rn.f32x2.
// Grid (4, 74) = 296 blocks = exactly 2/SM. Deterministic partials.
// ---------------------------------------------------------------------------
__global__ __launch_bounds__(240) void fc1_kernel(const float* __restrict__ fc1_w) {
    const int m0 = blockIdx.x * 64;
    const int k0 = blockIdx.y * KCHUNK;
    const int kend = min(k0 + KCHUNK, K_FC1);

    __shared__ float As[32][68];     // [kk][row], pad 4 -> float4-aligned rows
    __shared__ float Bs[32][120];    // [kk][n]

    const int tid = threadIdx.x;
    const int mg = tid & 15;         // 16 row-groups of 4
    const int ng = tid >> 4;         // 15 col-groups of 8

    unsigned long long acc2[2][8];   // row pairs (2i,2i+1) x 8 cols
#pragma unroll
    for (int i = 0; i < 2; i++)
#pragma unroll
        for (int j = 0; j < 8; j++) acc2[i][j] = 0ULL;

    for (int kb = k0; kb < kend; kb += 32) {
        // A tile: 64 rows x 32 k, maxpool of g_conv2 on the fly (k-minor = coalesced)
#pragma unroll
        for (int i = 0; i < 9; i++) {
            int idx = tid + i * 240;
            if (idx < 2048) {
                int r = idx >> 5, kk = idx & 31;
                int k = kb + kk;
                float v = 0.f;
                if (k < kend) {
                    int c = k / 3721;
                    int rem = k - c * 3721;
                    int y = rem / 61;
                    int xx = rem - y * 61;
                    const float* p = g_conv2 +
                        ((size_t)((m0 + r) * C2_OUT + c) * C2_H + y) * C2_H + xx;
                    v = fmaxf(fmaxf(p[0], p[1]), fmaxf(p[C2_H], p[C2_H + 1]));
                }
                As[kk][r] = v;
            }
        }
        // B tile: 120 n x 32 k (fc1_w is [120, 55815] row-major)
#pragma unroll
        for (int i = 0; i < 16; i++) {
            int idx = tid + i * 240;
            int n = idx >> 5, kk = idx & 31;
            int k = kb + kk;
            Bs[kk][n] = (k < kend) ? fc1_w[(size_t)n * K_FC1 + k] : 0.f;
        }
        __syncthreads();

#pragma unroll
        for (int kk = 0; kk < 32; kk++) {
            float4 a = *(const float4*)&As[kk][mg * 4];
            float4 b0 = *(const float4*)&Bs[kk][ng * 8];
            float4 b1 = *(const float4*)&Bs[kk][ng * 8 + 4];
            unsigned long long a01, a23, bb[8];
            PACK2(a01, a.x, a.y);
            PACK2(a23, a.z, a.w);
            BPACK(bb[0], b0.x); BPACK(bb[1], b0.y);
            BPACK(bb[2], b0.z); BPACK(bb[3], b0.w);
            BPACK(bb[4], b1.x); BPACK(bb[5], b1.y);
            BPACK(bb[6], b1.z); BPACK(bb[7], b1.w);
#pragma unroll
            for (int j = 0; j < 8; j++) {
                FMA2(acc2[0][j], a01, bb[j]);
                FMA2(acc2[1][j], a23, bb[j]);
            }
        }
        __syncthreads();
    }

    float* dst = g_fc1_part[blockIdx.y];
#pragma unroll
    for (int i = 0; i < 2; i++) {
        int row = m0 + mg * 4 + 2 * i;
#pragma unroll
        for (int j = 0; j < 8; j++) {
            float lo = __uint_as_float((unsigned)(acc2[i][j] & 0xffffffffULL));
            float hi = __uint_as_float((unsigned)(acc2[i][j] >> 32));
            dst[row * N_FC1 + ng * 8 + j] = lo;
            dst[(row + 1) * N_FC1 + ng * 8 + j] = hi;
        }
    }
}

// ---------------------------------------------------------------------------
// Head: reduce FC1 partials + bias + ReLU, FC2+ReLU, FC3, quantum statevector
// sim (4 qubits), softmax. One block per batch sample.
// ---------------------------------------------------------------------------
__global__ void head_kernel(const float* __restrict__ fc1_b,
                            const float* __restrict__ fc2_w,
                            const float* __restrict__ fc2_b,
                            const float* __restrict__ fc3_w,
                            const float* __restrict__ fc3_b,
                            const float* __restrict__ qw,
                            float* __restrict__ out) {
    const int b = blockIdx.x;
    __shared__ float h1[N_FC1];
    __shared__ float h2[N_FC2];
    __shared__ float ang[4];
    const int t = threadIdx.x;

    if (t < N_FC1) {
        float s = fc1_b[t];
#pragma unroll 8
        for (int j = 0; j < KSPLIT; j++) s += g_fc1_part[j][b * N_FC1 + t];
        h1[t] = fmaxf(s, 0.f);
    }
    __syncthreads();

    if (t < N_FC2) {
        float a = fc2_b[t];
#pragma unroll 8
        for (int k = 0; k < N_FC1; k++) a += h1[k] * fc2_w[t * N_FC1 + k];
        h2[t] = fmaxf(a, 0.f);
    }
    __syncthreads();

    if (t < 4) {
        float a = fc3_b[t];
#pragma unroll 4
        for (int k = 0; k < N_FC2; k++) a += h2[k] * fc3_w[t * N_FC2 + k];
        ang[t] = a;
    }
    __syncthreads();

    if (t == 0) {
        float sr[16], si[16];
#pragma unroll
        for (int i = 0; i < 16; i++) { sr[i] = 0.f; si[i] = 0.f; }
        sr[0] = 1.f;

        // RX encoding: gate [[c, -i s],[-i s, c]], wire q targets bit (3-q)
#pragma unroll
        for (int q = 0; q < 4; q++) {
            float th = ang[q] * 0.5f;
            float c = cosf(th), s = sinf(th);
            const int bit = 1 << (3 - q);
#pragma unroll
            for (int i0 = 0; i0 < 16; i0++) {
                if (i0 & bit) continue;
                int i1 = i0 | bit;
                float a0r = sr[i0], a0i = si[i0], a1r = sr[i1], a1i = si[i1];
                sr[i0] = c * a0r + s * a1i;  si[i0] = c * a0i - s * a1r;
                sr[i1] = c * a1r + s * a0i;  si[i1] = c * a1i - s * a0r;
            }
        }
        // DEPTH=2: RY layer (real gate [[c,-s],[s,c]]) + CZ chain
        int w = 0;
#pragma unroll
        for (int d = 0; d < 2; d++) {
#pragma unroll
            for (int q = 0; q < 4; q++) {
                float th = qw[w++] * 0.5f;
                float c = cosf(th), s = sinf(th);
                const int bit = 1 << (3 - q);
#pragma unroll
                for (int i0 = 0; i0 < 16; i0++) {
                    if (i0 & bit) continue;
                    int i1 = i0 | bit;
                    float a0r = sr[i0], a0i = si[i0], a1r = sr[i1], a1i = si[i1];
                    sr[i0] = c * a0r - s * a1r;  si[i0] = c * a0i - s * a1i;
                    sr[i1] = s * a0r + c * a1r;  si[i1] = s * a0i + c * a1i;
                }
            }
#pragma unroll
            for (int q = 0; q < 3; q++) {
                const int m1 = 1 << (3 - q), m2 = 1 << (2 - q);
#pragma unroll
                for (int i = 0; i < 16; i++)
                    if ((i & m1) && (i & m2)) { sr[i] = -sr[i]; si[i] = -si[i]; }
            }
        }
        float l0 = 0.f, l1 = 0.f;
#pragma unroll
        for (int i = 0; i < 16; i++) {
            float p = sr[i] * sr[i] + si[i] * si[i];
            l0 += (i & 8) ? -p : p;
            l1 += (i & 4) ? -p : p;
        }
        float m = fmaxf(l0, l1);
        float e0 = __expf(l0 - m), e1 = __expf(l1 - m);
        float inv = 1.f / (e0 + e1);
        out[b * 2 + 0] = e0 * inv;
        out[b * 2 + 1] = e1 * inv;
    }
}

// ---------------------------------------------------------------------------
extern "C" void kernel_launch(void* const* d_in, const int* in_sizes, int n_in,
                              void* d_out, int out_size) {
    const float* x     = (const float*)d_in[0];
    const float* w1    = (const float*)d_in[1];
    const float* b1    = (const float*)d_in[2];
    const float* w2    = (const float*)d_in[3];
    const float* b2    = (const float*)d_in[4];
    const float* fc1_w = (const float*)d_in[5];
    const float* fc1_b = (const float*)d_in[6];
    const float* fc2_w = (const float*)d_in[7];
    const float* fc2_b = (const float*)d_in[8];
    const float* fc3_w = (const float*)d_in[9];
    const float* fc3_b = (const float*)d_in[10];
    const float* qw    = (const float*)d_in[11];
    float* out = (float*)d_out;

    cudaFuncSetAttribute(conv1_kernel, cudaFuncAttributeMaxDynamicSharedMemorySize, C1_SMEM_BYTES);
    cudaFuncSetAttribute(conv2_kernel, cudaFuncAttributeMaxDynamicSharedMemorySize, C2_SMEM_BYTES);

    dim3 blk(16, 16);
    conv1_kernel<<<dim3(4, 4, BATCH), blk, C1_SMEM_BYTES>>>(x, w1, b1);
    conv2_kernel<<<dim3(2, 2, BATCH), blk, C2_SMEM_BYTES>>>(w2, b2);
    fc1_kernel<<<dim3(4, KSPLIT), 240>>>(fc1_w);
    head_kernel<<<BATCH, 128>>>(fc1_b, fc2_w, fc2_b, fc3_w, fc3_b, qw, out);
}